// round 12
// baseline (speedup 1.0000x reference)
#include <cuda_runtime.h>
#include <cuda_bf16.h>
#include <cstdint>

// Fused gamma-pdf-weighted MSE mean reduction — warp-specialized HYBRID:
// warps 0-6 stream via LDG.256 (L1tex path), warp 7 streams via a private
// 4-stage TMA ring (cp.async.bulk path). The two SM-side load engines
// throttle independently at ~5.0 / ~4.5 TB/s; running both concurrently
// targets the shared LTS/DRAM ceiling instead of either engine.
//
// math: mean( 0.5*(output-target)^2 * ef(target) )
// ef(y) = (BETA - c)*(1 - pdf(y)/FX_MAX) + c; pdf/FX_MAX < 4e-19 for fp32
// uniform targets except exact zeros -> log/exp only in cold branch.

#define NBLK    740          // 148 SMs * 5
#define NTH     256
#define LDG_NTH 224          // warps 0-6
#define TILE_F  1024         // floats per buffer per TMA tile
#define TILE_B  (TILE_F * 4) // 4096 bytes
#define NSTG    4

__device__ float        g_part[NBLK];
__device__ unsigned int g_count;   // zero-init; self-resetting via atomicInc wrap

// ---------------- math ----------------
__device__ __forceinline__ float elem_val(float o, float y) {
    const float A1        = -0.9355570857535674f;            // EST_A - 1
    const float NEG_LOC   = 1.1328205299926424e-27f;         // -EST_LOC
    const float INV_SCALE = (float)(1.0 / 1.5376362609160314);
    const float C0        = -58.4492351f;                    // -lgamma(a)-ln(scale)-ln(FX_MAX)
    const float C         = (float)(1.0 / 107.2185);
    const float BC        = 5.0f - (float)(1.0 / 107.2185);

    float r = 0.0f;
    if (y < 1e-6f) {                      // cold path: only (near-)zero targets
        float x  = (y + NEG_LOC) * INV_SCALE;
        float lp = fmaf(A1, __logf(x), C0) - x;
        r = __expf(lp);
    }
    float ef   = fmaf(BC, 1.0f - r, C);
    float diff = o - y;
    return 0.5f * diff * diff * ef;
}

__device__ __forceinline__ void ldg256(const float* __restrict__ p, float r[8]) {
    asm volatile("ld.global.nc.v8.f32 {%0,%1,%2,%3,%4,%5,%6,%7}, [%8];"
                 : "=f"(r[0]), "=f"(r[1]), "=f"(r[2]), "=f"(r[3]),
                   "=f"(r[4]), "=f"(r[5]), "=f"(r[6]), "=f"(r[7])
                 : "l"(p));
}

__device__ __forceinline__ float oct_val(const float o[8], const float t[8]) {
    float s = 0.0f;
    #pragma unroll
    for (int j = 0; j < 8; ++j) s += elem_val(o[j], t[j]);
    return s;
}

__device__ __forceinline__ float quad_val(float4 o, float4 t) {
    return elem_val(o.x, t.x) + elem_val(o.y, t.y)
         + elem_val(o.z, t.z) + elem_val(o.w, t.w);
}

// ---------------- PTX helpers ----------------
__device__ __forceinline__ uint32_t smem_u32(const void* p) {
    uint32_t a;
    asm("{ .reg .u64 t; cvta.to.shared.u64 t, %1; cvt.u32.u64 %0, t; }"
        : "=r"(a) : "l"(p));
    return a;
}
__device__ __forceinline__ void mbar_init(uint32_t mbar, uint32_t count) {
    asm volatile("mbarrier.init.shared.b64 [%0], %1;"
                 :: "r"(mbar), "r"(count) : "memory");
}
__device__ __forceinline__ void mbar_expect_tx(uint32_t mbar, uint32_t bytes) {
    asm volatile("mbarrier.arrive.expect_tx.shared.b64 _, [%0], %1;"
                 :: "r"(mbar), "r"(bytes) : "memory");
}
__device__ __forceinline__ void mbar_wait(uint32_t mbar, uint32_t parity) {
    uint32_t done;
    do {
        asm volatile(
            "{ .reg .pred p;\n"
            "  mbarrier.try_wait.parity.shared.b64 p, [%1], %2, 0x989680;\n"
            "  selp.b32 %0, 1, 0, p; }"
            : "=r"(done) : "r"(mbar), "r"(parity) : "memory");
    } while (!done);
}
__device__ __forceinline__ void bulk_ld(uint32_t dst, const float* src,
                                        uint32_t bytes, uint32_t mbar) {
    asm volatile(
        "cp.async.bulk.shared::cluster.global.mbarrier::complete_tx::bytes "
        "[%0], [%1], %2, [%3];"
        :: "r"(dst), "l"(src), "r"(bytes), "r"(mbar) : "memory");
}
__device__ __forceinline__ void fence_proxy_async_shared() {
    asm volatile("fence.proxy.async.shared::cta;" ::: "memory");
}

// ---------------- kernel ----------------
// P        : floats handled by the LDG path (prefix)
// tiles_pb : TMA tiles per block; TMA covers [P, P + NBLK*tiles_pb*TILE_F)
__global__ __launch_bounds__(NTH, 5) void loss_hybrid_kernel(
    const float* __restrict__ out, const float* __restrict__ tgt,
    float* __restrict__ result, int n, int P, int tiles_pb)
{
    __shared__ alignas(128) float    s_o[NSTG][TILE_F];
    __shared__ alignas(128) float    s_t[NSTG][TILE_F];
    __shared__ alignas(8)   uint64_t s_mbar[NSTG];
    __shared__ float s_warp[NTH / 32];
    __shared__ bool  s_last;

    const int tid  = threadIdx.x;
    const int lane = tid & 31;
    const int warp = tid >> 5;

    float sum = 0.0f;

    if (warp == 7) {
        // ================= TMA ring path (single warp, no block syncs) ====
        uint32_t mb[NSTG];
        #pragma unroll
        for (int s = 0; s < NSTG; ++s) mb[s] = smem_u32(&s_mbar[s]);

        if (lane == 0) {
            #pragma unroll
            for (int s = 0; s < NSTG; ++s) mbar_init(mb[s], 1);
            fence_proxy_async_shared();
        }
        __syncwarp();

        const long long tile0 = (long long)blockIdx.x * tiles_pb;

        if (lane == 0) {                    // prologue: fill all stages
            for (int k = 0; k < NSTG && k < tiles_pb; ++k) {
                const float* po = out + (size_t)P + (size_t)(tile0 + k) * TILE_F;
                const float* pt = tgt + (size_t)P + (size_t)(tile0 + k) * TILE_F;
                mbar_expect_tx(mb[k], 2 * TILE_B);
                bulk_ld(smem_u32(&s_o[k][0]), po, TILE_B, mb[k]);
                bulk_ld(smem_u32(&s_t[k][0]), pt, TILE_B, mb[k]);
            }
        }
        __syncwarp();

        for (int k = 0; k < tiles_pb; ++k) {
            const int s  = k & (NSTG - 1);
            const int ph = (k >> 2) & 1;
            mbar_wait(mb[s], ph);           // all 32 lanes

            const float4* so = (const float4*)&s_o[s][0];
            const float4* st = (const float4*)&s_t[s][0];
            #pragma unroll
            for (int j = 0; j < TILE_F / 4 / 32; ++j) {   // 8 float4 per lane
                int id = lane + j * 32;
                sum += quad_val(so[id], st[id]);
            }
            __syncwarp();                   // whole warp done with stage s

            if (lane == 0 && k + NSTG < tiles_pb) {
                const float* po = out + (size_t)P + (size_t)(tile0 + k + NSTG) * TILE_F;
                const float* pt = tgt + (size_t)P + (size_t)(tile0 + k + NSTG) * TILE_F;
                mbar_expect_tx(mb[s], 2 * TILE_B);
                bulk_ld(smem_u32(&s_o[s][0]), po, TILE_B, mb[s]);
                bulk_ld(smem_u32(&s_t[s][0]), pt, TILE_B, mb[s]);
            }
            __syncwarp();
        }
    } else {
        // ================= LDG path (warps 0-6) ===========================
        const int idx    = blockIdx.x * LDG_NTH + tid;
        const int stride = NBLK * LDG_NTH;
        const int p8     = P >> 3;

        int i = idx;
        for (; i + stride < p8; i += 2 * stride) {
            float o0[8], t0[8], o1[8], t1[8];
            ldg256(out + (size_t)i * 8,            o0);
            ldg256(tgt + (size_t)i * 8,            t0);
            ldg256(out + (size_t)(i + stride) * 8, o1);
            ldg256(tgt + (size_t)(i + stride) * 8, t1);
            sum += oct_val(o0, t0);
            sum += oct_val(o1, t1);
        }
        for (; i < p8; i += stride) {
            float o0[8], t0[8];
            ldg256(out + (size_t)i * 8, o0);
            ldg256(tgt + (size_t)i * 8, t0);
            sum += oct_val(o0, t0);
        }
        for (int j = (p8 << 3) + idx; j < P; j += stride)   // P%8 tail
            sum += elem_val(out[j], tgt[j]);
        // any floats beyond P + tma span (host guarantees none normally)
        const int tma_end = P + NBLK * tiles_pb * TILE_F;
        for (int j = tma_end + idx; j < n; j += stride)
            sum += elem_val(out[j], tgt[j]);
    }

    // ---- block reduce over all 8 warps ----
    #pragma unroll
    for (int off = 16; off > 0; off >>= 1)
        sum += __shfl_down_sync(0xFFFFFFFFu, sum, off);
    if (lane == 0) s_warp[warp] = sum;
    __syncthreads();

    if (warp == 0) {                      // full warp active
        float v = (lane < NTH / 32) ? s_warp[lane] : 0.0f;
        #pragma unroll
        for (int off = 16; off > 0; off >>= 1)
            v += __shfl_down_sync(0xFFFFFFFFu, v, off);
        if (lane == 0) {
            g_part[blockIdx.x] = v;
            __threadfence();                                   // release
            unsigned int prev = atomicInc(&g_count, NBLK - 1u); // wraps -> 0
            s_last = (prev == NBLK - 1u);
        }
    }
    __syncthreads();

    if (s_last) {
        __threadfence();                  // acquire before reading g_part
        double acc = 0.0;                 // fixed-order deterministic reduce
        for (int k = tid; k < NBLK; k += NTH)
            acc += (double)g_part[k];

        #pragma unroll
        for (int off = 16; off > 0; off >>= 1)
            acc += __shfl_down_sync(0xFFFFFFFFu, acc, off);

        __shared__ double s_d[NTH / 32];
        if (lane == 0) s_d[warp] = acc;
        __syncthreads();

        if (warp == 0) {                  // full warp active
            double v = (lane < NTH / 32) ? s_d[lane] : 0.0;
            #pragma unroll
            for (int off = 16; off > 0; off >>= 1)
                v += __shfl_down_sync(0xFFFFFFFFu, v, off);
            if (lane == 0)
                result[0] = (float)(v / (double)n);
        }
    }
}

extern "C" void kernel_launch(void* const* d_in, const int* in_sizes, int n_in,
                              void* d_out, int out_size)
{
    const float* output = (const float*)d_in[0];
    const float* target = (const float*)d_in[1];
    const int n = in_sizes[0];

    // TMA share ~45% of floats, rounded to whole tiles per block; needs
    // 16B-aligned tile bases -> P must be a multiple of 4 floats.
    int tiles_pb = 0;
    if ((n & 3) == 0) {
        long long q_target = (long long)((double)n * 0.45);
        tiles_pb = (int)(q_target / ((long long)TILE_F * NBLK));
    }
    int P = n - NBLK * tiles_pb * TILE_F;   // multiple of 4 when tiles_pb > 0

    loss_hybrid_kernel<<<NBLK, NTH>>>(output, target, (float*)d_out,
                                      n, P, tiles_pb);
}

// round 13
// speedup vs baseline: 1.1405x; 1.1405x over previous
#include <cuda_runtime.h>
#include <cuda_bf16.h>
#include <cstdint>

// Fused gamma-pdf-weighted MSE mean reduction — single kernel, last-block-done,
// 256-bit L1-BYPASS loads (ld.global.cv).
//
// mean( 0.5*(output-target)^2 * ef(target) )
// ef(y) = (BETA - c)*(1 - pdf(y)/FX_MAX) + c,  c = 1/(Y_MAX - Y_MIN)
// pdf/FX_MAX < 4e-19 for fp32 uniform targets except exact zeros ->
// log/exp only in a cold branch (y < 1e-6); hot loop has no MUFU.
//
// R13 rationale: B300_MICROARCH's ~6300 B/cyc chip cap was measured with
// LDG.cv (and TMA) — NOT the L1-allocating .nc path every prior round used.
// Streaming data is touched once and L1 is flushed per launch; the L1
// allocate/writeback round-trip is pure overhead and the prime suspect for
// the 5.0 TB/s plateau that was invariant under MLP, occupancy, width,
// and cache hints. .cv fetches straight from L2, no L1 allocation.

#define NBLK 740    // 148 SMs * 5
#define NTH  256

__device__ float        g_part[NBLK];
__device__ unsigned int g_count;   // zero-init; self-resetting via atomicInc wrap

__device__ __forceinline__ float elem_val(float o, float y) {
    const float A1        = -0.9355570857535674f;            // EST_A - 1
    const float NEG_LOC   = 1.1328205299926424e-27f;         // -EST_LOC
    const float INV_SCALE = (float)(1.0 / 1.5376362609160314);
    const float C0        = -58.4492351f;                    // -lgamma(a)-ln(scale)-ln(FX_MAX)
    const float C         = (float)(1.0 / 107.2185);
    const float BC        = 5.0f - (float)(1.0 / 107.2185);

    float r = 0.0f;
    if (y < 1e-6f) {                      // cold path: only (near-)zero targets
        float x  = (y + NEG_LOC) * INV_SCALE;
        float lp = fmaf(A1, __logf(x), C0) - x;
        r = __expf(lp);
    }
    float ef   = fmaf(BC, 1.0f - r, C);
    float diff = o - y;
    return 0.5f * diff * diff * ef;
}

// 256-bit global load, L1-bypass (.cv): fetch from L2, no L1 allocation.
__device__ __forceinline__ void ldg256_cv(const float* __restrict__ p, float r[8]) {
    asm volatile("ld.global.cv.v8.f32 {%0,%1,%2,%3,%4,%5,%6,%7}, [%8];"
                 : "=f"(r[0]), "=f"(r[1]), "=f"(r[2]), "=f"(r[3]),
                   "=f"(r[4]), "=f"(r[5]), "=f"(r[6]), "=f"(r[7])
                 : "l"(p));
}

__device__ __forceinline__ float oct_val(const float o[8], const float t[8]) {
    float s = 0.0f;
    #pragma unroll
    for (int j = 0; j < 8; ++j) s += elem_val(o[j], t[j]);
    return s;
}

__global__ __launch_bounds__(NTH, 5) void loss_fused_kernel(
    const float* __restrict__ out, const float* __restrict__ tgt,
    float* __restrict__ result, int n)
{
    const int tid    = threadIdx.x;
    const int lane   = tid & 31;
    const int warp   = tid >> 5;
    const int idx    = blockIdx.x * NTH + tid;
    const int stride = gridDim.x * NTH;
    const int n8     = n >> 3;            // v8 chunks

    float sum = 0.0f;
    int i = idx;

    // Unroll-by-2: 4 x LDG.256 (L1-bypass) issued before compute.
    for (; i + stride < n8; i += 2 * stride) {
        float o0[8], t0[8], o1[8], t1[8];
        ldg256_cv(out + (size_t)i * 8,            o0);
        ldg256_cv(tgt + (size_t)i * 8,            t0);
        ldg256_cv(out + (size_t)(i + stride) * 8, o1);
        ldg256_cv(tgt + (size_t)(i + stride) * 8, t1);
        sum += oct_val(o0, t0);
        sum += oct_val(o1, t1);
    }
    for (; i < n8; i += stride) {          // v8 remainder
        float o0[8], t0[8];
        ldg256_cv(out + (size_t)i * 8, o0);
        ldg256_cv(tgt + (size_t)i * 8, t0);
        sum += oct_val(o0, t0);
    }
    for (int j = (n8 << 3) + idx; j < n; j += stride)   // scalar tail
        sum += elem_val(out[j], tgt[j]);

    // ---- block reduce (full-warp shuffles only) ----
    #pragma unroll
    for (int off = 16; off > 0; off >>= 1)
        sum += __shfl_down_sync(0xFFFFFFFFu, sum, off);

    __shared__ float s_warp[NTH / 32];
    __shared__ bool  s_last;
    if (lane == 0) s_warp[warp] = sum;
    __syncthreads();

    if (warp == 0) {                      // full warp active
        float v = (lane < NTH / 32) ? s_warp[lane] : 0.0f;
        #pragma unroll
        for (int off = 16; off > 0; off >>= 1)
            v += __shfl_down_sync(0xFFFFFFFFu, v, off);
        if (lane == 0) {
            g_part[blockIdx.x] = v;
            __threadfence();                                   // release
            unsigned int prev = atomicInc(&g_count, NBLK - 1u); // wraps -> 0
            s_last = (prev == NBLK - 1u);
        }
    }
    __syncthreads();

    if (s_last) {
        __threadfence();                  // acquire before reading g_part
        double acc = 0.0;                 // fixed-order deterministic reduce
        for (int k = tid; k < NBLK; k += NTH)
            acc += (double)g_part[k];

        #pragma unroll
        for (int off = 16; off > 0; off >>= 1)
            acc += __shfl_down_sync(0xFFFFFFFFu, acc, off);

        __shared__ double s_d[NTH / 32];
        if (lane == 0) s_d[warp] = acc;
        __syncthreads();

        if (warp == 0) {                  // full warp active
            double v = (lane < NTH / 32) ? s_d[lane] : 0.0;
            #pragma unroll
            for (int off = 16; off > 0; off >>= 1)
                v += __shfl_down_sync(0xFFFFFFFFu, v, off);
            if (lane == 0)
                result[0] = (float)(v / (double)n);
        }
    }
}

extern "C" void kernel_launch(void* const* d_in, const int* in_sizes, int n_in,
                              void* d_out, int out_size)
{
    const float* output = (const float*)d_in[0];
    const float* target = (const float*)d_in[1];
    const int n = in_sizes[0];

    loss_fused_kernel<<<NBLK, NTH>>>(output, target, (float*)d_out, n);
}